// round 2
// baseline (speedup 1.0000x reference)
#include <cuda_runtime.h>
#include <cstdint>

// ---------------------------------------------------------------------------
// MLA QKV GEMM: fused DeepSeek MLA q/kv projection preprocessing.
//   hidden (2,4096,4096) f32
//   q:  rms(hidden @ q_a_w^T) @ q_b_w^T   -> per-head (nope | deepseek-T(pe))
//   kv: hidden @ kv_a_w^T -> [ckv(512) | k_pe(64)]
//       rms(ckv) @ kv_b_w^T -> per-head (k_nope | value)
//   out (2, 96, 4096, 192) f32 = concat([query, key, v_pad], axis=1)
// Strategy R1: TF32 mma.sync tiled GEMMs with fused scatter epilogues.
// ---------------------------------------------------------------------------

#define TOKENS   8192          // 2*4096
#define SEQ      4096
#define NHEAD    32
#define D_Q      192
#define D_NOPE   128
#define D_ROPE   64
#define R_KV     512
#define OUT_CH   96            // 3*NHEAD

// scratch (alloc-free rule: __device__ globals)
__device__ float g_qa  [TOKENS * 1536];
__device__ float g_ckv [TOKENS * 576];
__device__ float g_ckvn[TOKENS * 512];

__device__ __forceinline__ uint32_t f2tf(float f) {
    uint32_t r;
    asm("cvt.rna.tf32.f32 %0, %1;" : "=r"(r) : "f"(f));
    return r;
}

__device__ __forceinline__ void mma8(float c[4], const uint32_t a[4], const uint32_t b[2]) {
    asm volatile(
        "mma.sync.aligned.m16n8k8.row.col.f32.tf32.tf32.f32 "
        "{%0,%1,%2,%3},{%4,%5,%6,%7},{%8,%9},{%0,%1,%2,%3};"
        : "+f"(c[0]), "+f"(c[1]), "+f"(c[2]), "+f"(c[3])
        : "r"(a[0]), "r"(a[1]), "r"(a[2]), "r"(a[3]), "r"(b[0]), "r"(b[1]));
}

// EPI: 0 = plain C[t*N+n], 1 = query scatter, 2 = key/value scatter
template <int EPI>
__device__ __forceinline__ void epi_store(float* __restrict__ C, int t, int n, int N, float v) {
    if (EPI == 0) {
        C[(size_t)t * N + n] = v;
        return;
    }
    const int b = t >> 12;
    const int s = t & (SEQ - 1);
    if (EPI == 1) {
        // n = h*192 + d ; d<128 -> nope col d ; else pe with deepseek transpose
        const int h = n / D_Q;
        const int d = n - h * D_Q;
        int col;
        if (d < D_NOPE) {
            col = d;
        } else {
            const int j = d - D_NOPE;            // 0..63
            col = D_NOPE + (j >> 1) + ((j & 1) << 5);
        }
        C[((size_t)((b * OUT_CH + h) * SEQ + s)) * D_Q + col] = v;
    } else {
        // n = h*256 + d ; d<128 -> key ch (32+h) col d ; else value ch (64+h) col d-128
        const int h  = n >> 8;
        const int d  = n & 255;
        const int ch = (d < 128) ? (NHEAD + h) : (2 * NHEAD + h);
        const int col = d & 127;
        C[((size_t)((b * OUT_CH + ch) * SEQ + s)) * D_Q + col] = v;
    }
}

// ---------------------------------------------------------------------------
// TF32 GEMM: C[M,N] = A[M,K] (row-major) * W[N,K]^T
// BM=128, BN=128, BK=32, 256 threads (8 warps, 2x4), warp tile 64x32,
// single-buffered padded smem + register-staged global prefetch.
// ---------------------------------------------------------------------------
template <int EPI>
__global__ void __launch_bounds__(256)
gemm_tf32(const float* __restrict__ A, const float* __restrict__ W,
          float* __restrict__ C, int M, int N, int K)
{
    __shared__ uint32_t sA[128][33];
    __shared__ uint32_t sB[128][33];

    const int tid   = threadIdx.x;
    const int lane  = tid & 31;
    const int wrp   = tid >> 5;
    const int warpM = wrp >> 2;          // 0..1 -> 64-row slab
    const int warpN = wrp & 3;           // 0..3 -> 32-col slab
    const int bm = blockIdx.y;
    const int bn = blockIdx.x;

    float acc[4][4][4];
#pragma unroll
    for (int i = 0; i < 4; i++)
#pragma unroll
        for (int j = 0; j < 4; j++)
#pragma unroll
            for (int k = 0; k < 4; k++) acc[i][j][k] = 0.f;

    int lrow[4], lcol[4];
#pragma unroll
    for (int i = 0; i < 4; i++) {
        const int lin = tid + i * 256;   // 0..1023
        lrow[i] = lin >> 3;              // 0..127
        lcol[i] = (lin & 7) << 2;        // 0,4,...,28
    }

    const float* Abase = A + (size_t)(bm * 128) * K;
    const int ktiles = K >> 5;

    float4 ra[4], rb[4];
#pragma unroll
    for (int i = 0; i < 4; i++) {
        ra[i] = *(const float4*)(Abase + (size_t)lrow[i] * K + lcol[i]);
        const int gn = bn * 128 + lrow[i];
        rb[i] = (gn < N) ? *(const float4*)(W + (size_t)gn * K + lcol[i])
                         : make_float4(0.f, 0.f, 0.f, 0.f);
    }

    for (int kt = 0; kt < ktiles; kt++) {
        // stage registers -> smem (convert to tf32)
#pragma unroll
        for (int i = 0; i < 4; i++) {
            sA[lrow[i]][lcol[i] + 0] = f2tf(ra[i].x);
            sA[lrow[i]][lcol[i] + 1] = f2tf(ra[i].y);
            sA[lrow[i]][lcol[i] + 2] = f2tf(ra[i].z);
            sA[lrow[i]][lcol[i] + 3] = f2tf(ra[i].w);
            sB[lrow[i]][lcol[i] + 0] = f2tf(rb[i].x);
            sB[lrow[i]][lcol[i] + 1] = f2tf(rb[i].y);
            sB[lrow[i]][lcol[i] + 2] = f2tf(rb[i].z);
            sB[lrow[i]][lcol[i] + 3] = f2tf(rb[i].w);
        }
        __syncthreads();

        // prefetch next k-tile while computing this one
        if (kt + 1 < ktiles) {
            const int ko = (kt + 1) << 5;
#pragma unroll
            for (int i = 0; i < 4; i++) {
                ra[i] = *(const float4*)(Abase + (size_t)lrow[i] * K + ko + lcol[i]);
                const int gn = bn * 128 + lrow[i];
                rb[i] = (gn < N) ? *(const float4*)(W + (size_t)gn * K + ko + lcol[i])
                                 : make_float4(0.f, 0.f, 0.f, 0.f);
            }
        }

#pragma unroll
        for (int ks = 0; ks < 4; ks++) {
            const int k0 = (ks << 3) + (lane & 3);
            uint32_t af[4][4];
#pragma unroll
            for (int mi = 0; mi < 4; mi++) {
                const int r = warpM * 64 + mi * 16 + (lane >> 2);
                af[mi][0] = sA[r][k0];
                af[mi][1] = sA[r + 8][k0];
                af[mi][2] = sA[r][k0 + 4];
                af[mi][3] = sA[r + 8][k0 + 4];
            }
            uint32_t bf[4][2];
#pragma unroll
            for (int ni = 0; ni < 4; ni++) {
                const int c = warpN * 32 + ni * 8 + (lane >> 2);
                bf[ni][0] = sB[c][k0];
                bf[ni][1] = sB[c][k0 + 4];
            }
#pragma unroll
            for (int mi = 0; mi < 4; mi++)
#pragma unroll
                for (int ni = 0; ni < 4; ni++)
                    mma8(acc[mi][ni], af[mi], bf[ni]);
        }
        __syncthreads();
    }

    // epilogue
#pragma unroll
    for (int mi = 0; mi < 4; mi++) {
        const int row = bm * 128 + warpM * 64 + mi * 16 + (lane >> 2);
#pragma unroll
        for (int ni = 0; ni < 4; ni++) {
            const int col = bn * 128 + warpN * 32 + ni * 8 + ((lane & 3) << 1);
            if (col < N) {   // N always even -> col+1 also in range
                epi_store<EPI>(C, row,     col,     N, acc[mi][ni][0]);
                epi_store<EPI>(C, row,     col + 1, N, acc[mi][ni][1]);
                epi_store<EPI>(C, row + 8, col,     N, acc[mi][ni][2]);
                epi_store<EPI>(C, row + 8, col + 1, N, acc[mi][ni][3]);
            }
        }
    }
}

// ---------------------------------------------------------------------------
// block-wide sum reduce (256 threads)
// ---------------------------------------------------------------------------
__device__ __forceinline__ float block_sum_256(float v) {
    __shared__ float red[8];
#pragma unroll
    for (int o = 16; o; o >>= 1) v += __shfl_xor_sync(0xffffffffu, v, o);
    const int w = threadIdx.x >> 5, l = threadIdx.x & 31;
    if (l == 0) red[w] = v;
    __syncthreads();
    float r = 0.f;
    if (w == 0) {
        r = (l < 8) ? red[l] : 0.f;
#pragma unroll
        for (int o = 4; o; o >>= 1) r += __shfl_xor_sync(0xffffffffu, r, o);
    }
    return r;   // valid in warp 0
}

// in-place rmsnorm, one block per row
__global__ void rmsnorm_inplace(float* __restrict__ x, const float* __restrict__ w, int D)
{
    float* row = x + (size_t)blockIdx.x * D;
    float ss = 0.f;
    for (int j = threadIdx.x; j < D; j += 256) {
        const float v = row[j];
        ss += v * v;
    }
    const float tot = block_sum_256(ss);
    __shared__ float s_scale;
    if (threadIdx.x == 0) s_scale = rsqrtf(tot / (float)D + 1e-6f);
    __syncthreads();
    const float sc = s_scale;
    for (int j = threadIdx.x; j < D; j += 256) row[j] = row[j] * sc * w[j];
}

// ckv (stride 576): normalize cols [0,512) -> ckvn (stride 512);
// scatter cols [512,576) (k_pe, deepseek-transposed) to all 32 key heads of out.
__global__ void rmsnorm_kv_kpe(const float* __restrict__ ckv, float* __restrict__ ckvn,
                               const float* __restrict__ w, float* __restrict__ out)
{
    const int t = blockIdx.x;
    const float* row = ckv + (size_t)t * 576;

    float ss = 0.f;
    for (int j = threadIdx.x; j < R_KV; j += 256) {
        const float v = row[j];
        ss += v * v;
    }
    const float tot = block_sum_256(ss);
    __shared__ float s_scale;
    if (threadIdx.x == 0) s_scale = rsqrtf(tot / (float)R_KV + 1e-6f);
    __syncthreads();
    const float sc = s_scale;
    for (int j = threadIdx.x; j < R_KV; j += 256)
        ckvn[(size_t)t * R_KV + j] = row[j] * sc * w[j];

    // k_pe scatter: thread -> (j = tid&63, head group = tid>>6, 8 heads each)
    const int b = t >> 12;
    const int s = t & (SEQ - 1);
    const int j  = threadIdx.x & 63;
    const int hg = threadIdx.x >> 6;          // 0..3
    const float v = row[R_KV + j];
    const int col = D_NOPE + (j >> 1) + ((j & 1) << 5);
#pragma unroll
    for (int hh = 0; hh < 8; hh++) {
        const int h = hg * 8 + hh;
        out[((size_t)((b * OUT_CH + NHEAD + h) * SEQ + s)) * D_Q + col] = v;
    }
}

// zero out[b, 64+h, s, 128:192] (value padding). One float4 per thread.
__global__ void zero_vpad(float* __restrict__ out)
{
    const int idx = blockIdx.x * blockDim.x + threadIdx.x;   // 0 .. 2*32*4096*16-1
    const int f = idx & 15;
    const int s = (idx >> 4) & (SEQ - 1);
    const int h = (idx >> 16) & 31;
    const int b = idx >> 21;
    float4* p = (float4*)(out + ((size_t)((b * OUT_CH + 2 * NHEAD + h) * SEQ + s)) * D_Q + D_NOPE) + f;
    *p = make_float4(0.f, 0.f, 0.f, 0.f);
}

// ---------------------------------------------------------------------------
extern "C" void kernel_launch(void* const* d_in, const int* in_sizes, int n_in,
                              void* d_out, int out_size)
{
    const float* hidden   = (const float*)d_in[0];
    const float* q_a_w    = (const float*)d_in[1];
    const float* q_b_w    = (const float*)d_in[2];
    const float* kv_a_w   = (const float*)d_in[3];
    const float* kv_b_w   = (const float*)d_in[4];
    const float* q_a_ln_w = (const float*)d_in[5];
    const float* kv_a_ln_w= (const float*)d_in[6];
    float* out = (float*)d_out;

    float *qa, *ckv, *ckvn;
    cudaGetSymbolAddress((void**)&qa,   g_qa);
    cudaGetSymbolAddress((void**)&ckv,  g_ckv);
    cudaGetSymbolAddress((void**)&ckvn, g_ckvn);

    const dim3 blk(256);

    // stage A: down-projections (read hidden twice; fuse candidates for R2)
    gemm_tf32<0><<<dim3(12, 64), blk>>>(hidden, q_a_w,  qa,  TOKENS, 1536, 4096);
    gemm_tf32<0><<<dim3(5,  64), blk>>>(hidden, kv_a_w, ckv, TOKENS, 576,  4096);

    // stage B: norms + k_pe scatter + v padding
    rmsnorm_inplace<<<TOKENS, 256>>>(qa, q_a_ln_w, 1536);
    rmsnorm_kv_kpe <<<TOKENS, 256>>>(ckv, ckvn, kv_a_ln_w, out);
    zero_vpad      <<<(2 * NHEAD * SEQ * 16) / 256, 256>>>(out);

    // stage C: up-projections with fused scatter epilogues
    gemm_tf32<1><<<dim3(48, 64), blk>>>(qa,   q_b_w,  out, TOKENS, 6144, 1536);
    gemm_tf32<2><<<dim3(64, 64), blk>>>(ckvn, kv_b_w, out, TOKENS, 8192, 512);
}

// round 8
// speedup vs baseline: 2.1437x; 2.1437x over previous
#include <cuda_runtime.h>
#include <cstdint>

// ---------------------------------------------------------------------------
// MLA QKV projection — R7: legacy mma.sync TF32 (tcgen05 unsupported by the
// harness toolchain: ptxas targets sm_103 without the 'a' feature set).
//   Block 128(tok) x 256(feat), BK=32, 8 warps, warp tile 64x64.
//   cp.async double-buffered smem, stride-36 rows -> conflict-free fragments.
//   Fused scatter epilogues into the (2,96,4096,192) output.
//   Scratch: separate __device__ arrays (R2-passing pattern, no aliasing).
// ---------------------------------------------------------------------------

#define TOKENS   8192
#define SEQ      4096
#define NHEAD    32
#define D_Q      192
#define D_NOPE   128
#define R_KV     512
#define OUT_CH   96

// ---------------- scratch (__device__ globals; no allocs allowed) ----------
__device__ float g_ht   [33554432];   // hidden  tf32  (2*4096*4096)
__device__ float g_w1   [6291456];    // q_a_w   tf32  (1536*4096)
__device__ float g_w2   [2359296];    // kv_a_w  tf32  (576*4096)
__device__ float g_w3   [9437184];    // q_b_w   tf32  (6144*1536)
__device__ float g_w4   [4194304];    // kv_b_w  tf32  (8192*512)
__device__ float g_qa   [12582912];   // f32 GEMM1 out (8192*1536)
__device__ float g_qat  [12582912];   // tf32 normed qa
__device__ float g_ckv  [4718592];    // f32 GEMM2 out (8192*576)
__device__ float g_ckvnt[4194304];    // tf32 normed ckv (8192*512)

__device__ __forceinline__ uint32_t f2tf(float f) {
    uint32_t r; asm("cvt.rna.tf32.f32 %0, %1;" : "=r"(r) : "f"(f)); return r;
}

__device__ __forceinline__ void mma8(float c[4], const uint32_t a[4], const uint32_t b[2]) {
    asm volatile(
        "mma.sync.aligned.m16n8k8.row.col.f32.tf32.tf32.f32 "
        "{%0,%1,%2,%3},{%4,%5,%6,%7},{%8,%9},{%0,%1,%2,%3};"
        : "+f"(c[0]), "+f"(c[1]), "+f"(c[2]), "+f"(c[3])
        : "r"(a[0]), "r"(a[1]), "r"(a[2]), "r"(a[3]), "r"(b[0]), "r"(b[1]));
}

__device__ __forceinline__ void cpa16(uint32_t dst, const void* src, int nbytes) {
    asm volatile("cp.async.cg.shared.global [%0], [%1], 16, %2;"
                 :: "r"(dst), "l"(src), "r"(nbytes));
}
#define CPA_COMMIT() asm volatile("cp.async.commit_group;" ::: "memory")
#define CPA_WAIT(n)  asm volatile("cp.async.wait_group %0;" :: "n"(n) : "memory")

// EPI: 0 = plain C[t*N+n], 1 = query scatter, 2 = key/value scatter
template <int EPI>
__device__ __forceinline__ void epi_store(float* __restrict__ C, int t, int n, int N, float v) {
    if (EPI == 0) {
        C[(size_t)t * N + n] = v;
        return;
    }
    const int b = t >> 12;
    const int s = t & (SEQ - 1);
    if (EPI == 1) {
        const int h = n / D_Q;
        const int d = n - h * D_Q;
        int col;
        if (d < D_NOPE) col = d;
        else {
            const int j = d - D_NOPE;
            col = D_NOPE + (j >> 1) + ((j & 1) << 5);
        }
        C[((size_t)((b * OUT_CH + h) * SEQ + s)) * D_Q + col] = v;
    } else {
        const int h  = n >> 8;
        const int d  = n & 255;
        const int ch = (d < 128) ? (NHEAD + h) : (2 * NHEAD + h);
        C[((size_t)((b * OUT_CH + ch) * SEQ + s)) * D_Q + (d & 127)] = v;
    }
}

// ---------------------------------------------------------------------------
// TF32 GEMM: C[M,N] = A[M,K] (tokens, tf32) * W[N,K]^T (features, tf32)
// BM=128, BN=256, BK=32; 256 threads = 8 warps (2 x 4), warp tile 64x64.
// smem rows stride 36 floats: fragment bank = (4r + k) mod 32 -> conflict-free.
// stage = 13824 floats (A 128x36 = 4608, B 256x36 = 9216), 2 stages, 110592 B.
// ---------------------------------------------------------------------------
template <int EPI>
__global__ void __launch_bounds__(256, 1)
gemm_tf32(const float* __restrict__ A, const float* __restrict__ W,
          float* __restrict__ C, int N, int K)
{
    extern __shared__ float smem[];

    const int tid   = threadIdx.x;
    const int lane  = tid & 31;
    const int wrp   = tid >> 5;
    const int warpM = wrp >> 2;            // 0..1 -> 64 token rows
    const int warpN = wrp & 3;             // 0..3 -> 64 feature cols
    const int t0    = blockIdx.y * 128;
    const int n0    = blockIdx.x * 256;

    float acc[4][8][4];
#pragma unroll
    for (int i = 0; i < 4; i++)
#pragma unroll
        for (int j = 0; j < 8; j++)
#pragma unroll
            for (int k = 0; k < 4; k++) acc[i][j][k] = 0.f;

    const int KT = K >> 5;

    auto load_tile = [&](int s, int kt) {
        const int kk = kt * 32;
        float* sA = smem + s * 13824;
        float* sB = sA + 4608;
        // A: 128 rows x 32 -> 1024 float4, 4 per thread
#pragma unroll
        for (int i = 0; i < 4; i++) {
            const int f = tid + i * 256;
            const int row = f >> 3, cq = (f & 7) << 2;
            const uint32_t dst = (uint32_t)__cvta_generic_to_shared(sA + row * 36 + cq);
            cpa16(dst, A + (size_t)(t0 + row) * K + kk + cq, 16);
        }
        // B: 256 rows x 32 -> 2048 float4, 8 per thread (zero-fill past N)
#pragma unroll
        for (int i = 0; i < 8; i++) {
            const int f = tid + i * 256;
            const int row = f >> 3, cq = (f & 7) << 2;
            const int gn = n0 + row;
            const uint32_t dst = (uint32_t)__cvta_generic_to_shared(sB + row * 36 + cq);
            const int ok = (gn < N) ? 16 : 0;
            cpa16(dst, W + (size_t)(ok ? gn : 0) * K + kk + cq, ok);
        }
        CPA_COMMIT();
    };

    load_tile(0, 0);
    if (KT > 1) load_tile(1, 1);

    for (int kt = 0; kt < KT; kt++) {
        if (kt + 1 < KT) CPA_WAIT(1); else CPA_WAIT(0);
        __syncthreads();

        const float* sA = smem + (kt & 1) * 13824;
        const float* sB = sA + 4608;
        const uint32_t* uA = (const uint32_t*)sA;
        const uint32_t* uB = (const uint32_t*)sB;

#pragma unroll
        for (int ks = 0; ks < 4; ks++) {
            const int k0 = (ks << 3) + (lane & 3);
            uint32_t a[4][4];
#pragma unroll
            for (int mi = 0; mi < 4; mi++) {
                const int r = warpM * 64 + mi * 16 + (lane >> 2);
                a[mi][0] = uA[r * 36 + k0];
                a[mi][1] = uA[(r + 8) * 36 + k0];
                a[mi][2] = uA[r * 36 + k0 + 4];
                a[mi][3] = uA[(r + 8) * 36 + k0 + 4];
            }
            uint32_t b[8][2];
#pragma unroll
            for (int ni = 0; ni < 8; ni++) {
                const int c = warpN * 64 + ni * 8 + (lane >> 2);
                b[ni][0] = uB[c * 36 + k0];
                b[ni][1] = uB[c * 36 + k0 + 4];
            }
#pragma unroll
            for (int mi = 0; mi < 4; mi++)
#pragma unroll
                for (int ni = 0; ni < 8; ni++)
                    mma8(acc[mi][ni], a[mi], b[ni]);
        }
        __syncthreads();
        if (kt + 2 < KT) load_tile(kt & 1, kt + 2);
    }

    // epilogue
#pragma unroll
    for (int mi = 0; mi < 4; mi++) {
        const int row = t0 + warpM * 64 + mi * 16 + (lane >> 2);
#pragma unroll
        for (int ni = 0; ni < 8; ni++) {
            const int col = n0 + warpN * 64 + ni * 8 + ((lane & 3) << 1);
            if (col < N) {   // N even -> col+1 also valid
                epi_store<EPI>(C, row,     col,     N, acc[mi][ni][0]);
                epi_store<EPI>(C, row,     col + 1, N, acc[mi][ni][1]);
                epi_store<EPI>(C, row + 8, col,     N, acc[mi][ni][2]);
                epi_store<EPI>(C, row + 8, col + 1, N, acc[mi][ni][3]);
            }
        }
    }
}

// ---------------------------------------------------------------------------
// f32 -> tf32(rna) pre-conversion
// ---------------------------------------------------------------------------
__global__ void conv_tf32(const float4* __restrict__ src, float4* __restrict__ dst, int n4)
{
    const int i = blockIdx.x * blockDim.x + threadIdx.x;
    if (i < n4) {
        float4 v = src[i];
        v.x = __uint_as_float(f2tf(v.x));
        v.y = __uint_as_float(f2tf(v.y));
        v.z = __uint_as_float(f2tf(v.z));
        v.w = __uint_as_float(f2tf(v.w));
        dst[i] = v;
    }
}

// ---------------------------------------------------------------------------
// norms (f32 in, tf32 out)
// ---------------------------------------------------------------------------
__device__ __forceinline__ float block_sum_256(float v) {
    __shared__ float red[8];
#pragma unroll
    for (int o = 16; o; o >>= 1) v += __shfl_xor_sync(0xffffffffu, v, o);
    const int w = threadIdx.x >> 5, l = threadIdx.x & 31;
    if (l == 0) red[w] = v;
    __syncthreads();
    float r = 0.f;
    if (w == 0) {
        r = (l < 8) ? red[l] : 0.f;
#pragma unroll
        for (int o = 4; o; o >>= 1) r += __shfl_xor_sync(0xffffffffu, r, o);
    }
    return r;
}

__global__ void rms_qa(const float* __restrict__ x, float* __restrict__ y,
                       const float* __restrict__ w)
{
    const float* row = x + (size_t)blockIdx.x * 1536;
    float* dst       = y + (size_t)blockIdx.x * 1536;
    float ss = 0.f;
    for (int j = threadIdx.x; j < 1536; j += 256) { const float v = row[j]; ss += v * v; }
    const float tot = block_sum_256(ss);
    __shared__ float s_sc;
    if (threadIdx.x == 0) s_sc = rsqrtf(tot / 1536.f + 1e-6f);
    __syncthreads();
    const float sc = s_sc;
    for (int j = threadIdx.x; j < 1536; j += 256)
        dst[j] = __uint_as_float(f2tf(row[j] * sc * w[j]));
}

__global__ void rms_kv_kpe(const float* __restrict__ ckv, float* __restrict__ ckvn,
                           const float* __restrict__ w, float* __restrict__ out)
{
    const int t = blockIdx.x;
    const float* row = ckv + (size_t)t * 576;
    float ss = 0.f;
    for (int j = threadIdx.x; j < R_KV; j += 256) { const float v = row[j]; ss += v * v; }
    const float tot = block_sum_256(ss);
    __shared__ float s_sc;
    if (threadIdx.x == 0) s_sc = rsqrtf(tot / (float)R_KV + 1e-6f);
    __syncthreads();
    const float sc = s_sc;
    for (int j = threadIdx.x; j < R_KV; j += 256)
        ckvn[(size_t)t * R_KV + j] = __uint_as_float(f2tf(row[j] * sc * w[j]));

    // k_pe scatter (raw f32, deepseek-transposed) to all 32 key heads
    const int b = t >> 12;
    const int s = t & (SEQ - 1);
    const int j  = threadIdx.x & 63;
    const int hg = threadIdx.x >> 6;
    const float v = row[R_KV + j];
    const int col = D_NOPE + (j >> 1) + ((j & 1) << 5);
#pragma unroll
    for (int hh = 0; hh < 8; hh++) {
        const int h = hg * 8 + hh;
        out[((size_t)((b * OUT_CH + NHEAD + h) * SEQ + s)) * D_Q + col] = v;
    }
}

__global__ void zero_vpad(float* __restrict__ out)
{
    const int idx = blockIdx.x * blockDim.x + threadIdx.x;
    const int f = idx & 15;
    const int s = (idx >> 4) & (SEQ - 1);
    const int h = (idx >> 16) & 31;
    const int b = idx >> 21;
    float4* p = (float4*)(out + ((size_t)((b * OUT_CH + 2 * NHEAD + h) * SEQ + s)) * D_Q + D_NOPE) + f;
    *p = make_float4(0.f, 0.f, 0.f, 0.f);
}

// ---------------------------------------------------------------------------
extern "C" void kernel_launch(void* const* d_in, const int* in_sizes, int n_in,
                              void* d_out, int out_size)
{
    const float* hidden    = (const float*)d_in[0];
    const float* q_a_w     = (const float*)d_in[1];
    const float* q_b_w     = (const float*)d_in[2];
    const float* kv_a_w    = (const float*)d_in[3];
    const float* kv_b_w    = (const float*)d_in[4];
    const float* q_a_ln_w  = (const float*)d_in[5];
    const float* kv_a_ln_w = (const float*)d_in[6];
    float* out = (float*)d_out;

    float *ht, *w1, *w2, *w3, *w4, *qa, *qat, *ckv, *ckvnt;
    cudaGetSymbolAddress((void**)&ht,    g_ht);
    cudaGetSymbolAddress((void**)&w1,    g_w1);
    cudaGetSymbolAddress((void**)&w2,    g_w2);
    cudaGetSymbolAddress((void**)&w3,    g_w3);
    cudaGetSymbolAddress((void**)&w4,    g_w4);
    cudaGetSymbolAddress((void**)&qa,    g_qa);
    cudaGetSymbolAddress((void**)&qat,   g_qat);
    cudaGetSymbolAddress((void**)&ckv,   g_ckv);
    cudaGetSymbolAddress((void**)&ckvnt, g_ckvnt);

    const int SMEM = 2 * 13824 * 4;   // 110592 B
    cudaFuncSetAttribute(gemm_tf32<0>, cudaFuncAttributeMaxDynamicSharedMemorySize, SMEM);
    cudaFuncSetAttribute(gemm_tf32<1>, cudaFuncAttributeMaxDynamicSharedMemorySize, SMEM);
    cudaFuncSetAttribute(gemm_tf32<2>, cudaFuncAttributeMaxDynamicSharedMemorySize, SMEM);

    // 1) pre-convert inputs to tf32 (rna)
    auto conv = [&](const float* s, float* d, int n) {
        const int n4 = n >> 2;
        conv_tf32<<<(n4 + 255) / 256, 256>>>((const float4*)s, (float4*)d, n4);
    };
    conv(hidden, ht, 33554432);
    conv(q_a_w,  w1, 6291456);
    conv(kv_a_w, w2, 2359296);
    conv(q_b_w,  w3, 9437184);
    conv(kv_b_w, w4, 4194304);

    const dim3 blk(256);

    // 2) down-projections
    gemm_tf32<0><<<dim3(6, 64), blk, SMEM>>>(ht, w1, qa,  1536, 4096);
    gemm_tf32<0><<<dim3(3, 64), blk, SMEM>>>(ht, w2, ckv, 576,  4096);

    // 3) norms + k_pe scatter + value padding
    rms_qa    <<<TOKENS, 256>>>(qa, qat, q_a_ln_w);
    rms_kv_kpe<<<TOKENS, 256>>>(ckv, ckvnt, kv_a_ln_w, out);
    zero_vpad <<<(2 * NHEAD * SEQ * 16) / 256, 256>>>(out);

    // 4) up-projections with fused scatter epilogues
    gemm_tf32<1><<<dim3(24, 64), blk, SMEM>>>(qat,   w3, out, 6144, 1536);
    gemm_tf32<2><<<dim3(32, 64), blk, SMEM>>>(ckvnt, w4, out, 8192, 512);
}

// round 9
// speedup vs baseline: 2.4448x; 1.1405x over previous
#include <cuda_runtime.h>
#include <cstdint>

// ---------------------------------------------------------------------------
// MLA QKV projection — R9: mma.sync TF32 + ldmatrix fragments + BK=64.
//   Block 128(tok) x 256(feat), BK=64, 8 warps, warp tile 64x64.
//   cp.async double-buffered smem (209 KB), stride-68 rows (conflict-free for
//   both LDSM fragments and cp.async stores).
//   Down-projections merged into one launch; fused scatter epilogues.
// ---------------------------------------------------------------------------

#define TOKENS   8192
#define SEQ      4096
#define NHEAD    32
#define D_Q      192
#define D_NOPE   128
#define R_KV     512
#define OUT_CH   96

// ---------------- scratch (__device__ globals; no allocs allowed) ----------
__device__ float g_ht   [33554432];   // hidden  tf32  (2*4096*4096)
__device__ float g_w12  [8650752];    // [q_a_w | kv_a_w] tf32 (2112*4096)
__device__ float g_w3   [9437184];    // q_b_w   tf32  (6144*1536)
__device__ float g_w4   [4194304];    // kv_b_w  tf32  (8192*512)
__device__ float g_qa   [12582912];   // f32 GEMM1 out (8192*1536)
__device__ float g_qat  [12582912];   // tf32 normed qa
__device__ float g_ckv  [4718592];    // f32 GEMM2 out (8192*576)
__device__ float g_ckvnt[4194304];    // tf32 normed ckv (8192*512)

__device__ __forceinline__ uint32_t f2tf(float f) {
    uint32_t r; asm("cvt.rna.tf32.f32 %0, %1;" : "=r"(r) : "f"(f)); return r;
}

__device__ __forceinline__ void mma8(float c[4], const uint32_t a[4], const uint32_t b[2]) {
    asm volatile(
        "mma.sync.aligned.m16n8k8.row.col.f32.tf32.tf32.f32 "
        "{%0,%1,%2,%3},{%4,%5,%6,%7},{%8,%9},{%0,%1,%2,%3};"
        : "+f"(c[0]), "+f"(c[1]), "+f"(c[2]), "+f"(c[3])
        : "r"(a[0]), "r"(a[1]), "r"(a[2]), "r"(a[3]), "r"(b[0]), "r"(b[1]));
}

// ldmatrix x4: four 8-row x 16-byte tiles -> 4 regs/thread.
// For tf32 data, one tile = 8 rows x 4 tf32; thread t receives the 32-bit
// value at (row t/4, col t%4) of tile (t/8 per-address-octet mapping below).
#define LDSM4(r, addr) \
    asm volatile("ldmatrix.sync.aligned.m8n8.x4.shared.b16 {%0,%1,%2,%3}, [%4];" \
        : "=r"((r)[0]), "=r"((r)[1]), "=r"((r)[2]), "=r"((r)[3]) : "r"(addr))

__device__ __forceinline__ void cpa16(uint32_t dst, const void* src, int nbytes) {
    asm volatile("cp.async.cg.shared.global [%0], [%1], 16, %2;"
                 :: "r"(dst), "l"(src), "r"(nbytes));
}
#define CPA_COMMIT() asm volatile("cp.async.commit_group;" ::: "memory")
#define CPA_WAIT(n)  asm volatile("cp.async.wait_group %0;" :: "n"(n) : "memory")

// EPI: 1 = query scatter, 2 = key/value scatter, 3 = merged down-proj (qa|ckv)
template <int EPI>
__device__ __forceinline__ void epi_store(float* __restrict__ C, float* __restrict__ C2,
                                          int t, int n, float v) {
    if (EPI == 3) {
        if (n < 1536) C [(size_t)t * 1536 + n] = v;
        else          C2[(size_t)t * 576 + (n - 1536)] = v;
        return;
    }
    const int b = t >> 12;
    const int s = t & (SEQ - 1);
    if (EPI == 1) {
        const int h = n / D_Q;
        const int d = n - h * D_Q;
        int col;
        if (d < D_NOPE) col = d;
        else {
            const int j = d - D_NOPE;
            col = D_NOPE + (j >> 1) + ((j & 1) << 5);
        }
        C[((size_t)((b * OUT_CH + h) * SEQ + s)) * D_Q + col] = v;
    } else {
        const int h  = n >> 8;
        const int d  = n & 255;
        const int ch = (d < 128) ? (NHEAD + h) : (2 * NHEAD + h);
        C[((size_t)((b * OUT_CH + ch) * SEQ + s)) * D_Q + (d & 127)] = v;
    }
}

// ---------------------------------------------------------------------------
// TF32 GEMM: C = A[M,K](tokens) * W[N,K]^T(features)
// BM=128, BN=256, BK=64; 256 threads = 8 warps (2 x 4), warp tile 64x64.
// smem row stride 68 floats; stage = 26112 floats; 2 stages = 208896 B.
// ---------------------------------------------------------------------------
template <int EPI>
__global__ void __launch_bounds__(256, 1)
gemm_tf32(const float* __restrict__ A, const float* __restrict__ W,
          float* __restrict__ C, float* __restrict__ C2, int N, int K)
{
    extern __shared__ float smem[];

    const int tid   = threadIdx.x;
    const int lane  = tid & 31;
    const int wrp   = tid >> 5;
    const int warpM = wrp >> 2;            // 0..1 -> 64 token rows
    const int warpN = wrp & 3;             // 0..3 -> 64 feature cols
    const int t0    = blockIdx.y * 128;
    const int n0    = blockIdx.x * 256;

    float acc[4][8][4];
#pragma unroll
    for (int i = 0; i < 4; i++)
#pragma unroll
        for (int j = 0; j < 8; j++)
#pragma unroll
            for (int k = 0; k < 4; k++) acc[i][j][k] = 0.f;

    const int KT = K >> 6;

    auto load_tile = [&](int s, int kt) {
        const int kk = kt * 64;
        float* sA = smem + s * 26112;
        float* sB = sA + 8704;
        // A: 128 rows x 64 -> 2048 float4, 8 per thread
#pragma unroll
        for (int i = 0; i < 8; i++) {
            const int f = tid + i * 256;
            const int row = f >> 4, cq = (f & 15) << 2;
            const uint32_t dst = (uint32_t)__cvta_generic_to_shared(sA + row * 68 + cq);
            cpa16(dst, A + (size_t)(t0 + row) * K + kk + cq, 16);
        }
        // B: 256 rows x 64 -> 4096 float4, 16 per thread (zero-fill past N)
#pragma unroll
        for (int i = 0; i < 16; i++) {
            const int f = tid + i * 256;
            const int row = f >> 4, cq = (f & 15) << 2;
            const int gn = n0 + row;
            const uint32_t dst = (uint32_t)__cvta_generic_to_shared(sB + row * 68 + cq);
            const int ok = (gn < N) ? 16 : 0;
            cpa16(dst, W + (size_t)(ok ? gn : 0) * K + kk + cq, ok);
        }
        CPA_COMMIT();
    };

    load_tile(0, 0);
    if (KT > 1) load_tile(1, 1);

    // ldmatrix octet decomposition: lm = matrix index (addr octet), lr = row
    const int lm = lane >> 3;
    const int lr = lane & 7;

    for (int kt = 0; kt < KT; kt++) {
        if (kt + 1 < KT) CPA_WAIT(1); else CPA_WAIT(0);
        __syncthreads();

        const float* sA = smem + (kt & 1) * 26112;
        const float* sB = sA + 8704;

        // Per-thread LDSM base addresses (bytes), one per mi / ni-pair.
        // A matrices m0..m3 = (row+0,k+0),(row+8,k+0),(row+0,k+4),(row+8,k+4)
        //   -> regs a[0..3] in exact mma order.
        // B matrices m0..m3 = (n+0,k+0),(n+0,k+4),(n+8,k+0),(n+8,k+4)
        //   -> regs b[0..1] for ni=2p, b[2..3] for ni=2p+1.
        uint32_t aAddr[4], bAddr[4];
        {
            const int ar = warpM * 64 + (lm & 1) * 8 + lr;
            const int ak = (lm >> 1) * 4;
#pragma unroll
            for (int mi = 0; mi < 4; mi++)
                aAddr[mi] = (uint32_t)__cvta_generic_to_shared(sA + (ar + mi * 16) * 68 + ak);
            const int br = warpN * 64 + (lm >> 1) * 8 + lr;
            const int bk = (lm & 1) * 4;
#pragma unroll
            for (int p = 0; p < 4; p++)
                bAddr[p] = (uint32_t)__cvta_generic_to_shared(sB + (br + p * 16) * 68 + bk);
        }

#pragma unroll
        for (int ks = 0; ks < 8; ks++) {
            uint32_t a[4][4], b[4][4];
#pragma unroll
            for (int mi = 0; mi < 4; mi++) LDSM4(a[mi], aAddr[mi] + ks * 32);
#pragma unroll
            for (int p = 0; p < 4; p++)   LDSM4(b[p],  bAddr[p]  + ks * 32);
#pragma unroll
            for (int mi = 0; mi < 4; mi++)
#pragma unroll
                for (int p = 0; p < 4; p++) {
                    mma8(acc[mi][2 * p],     a[mi], &b[p][0]);
                    mma8(acc[mi][2 * p + 1], a[mi], &b[p][2]);
                }
        }
        __syncthreads();
        if (kt + 2 < KT) load_tile(kt & 1, kt + 2);
    }

    // epilogue
#pragma unroll
    for (int mi = 0; mi < 4; mi++) {
        const int row = t0 + warpM * 64 + mi * 16 + (lane >> 2);
#pragma unroll
        for (int ni = 0; ni < 8; ni++) {
            const int col = n0 + warpN * 64 + ni * 8 + ((lane & 3) << 1);
            if (col < N) {   // N even -> col+1 also valid
                epi_store<EPI>(C, C2, row,     col,     acc[mi][ni][0]);
                epi_store<EPI>(C, C2, row,     col + 1, acc[mi][ni][1]);
                epi_store<EPI>(C, C2, row + 8, col,     acc[mi][ni][2]);
                epi_store<EPI>(C, C2, row + 8, col + 1, acc[mi][ni][3]);
            }
        }
    }
}

// ---------------------------------------------------------------------------
// f32 -> tf32(rna) pre-conversion
// ---------------------------------------------------------------------------
__global__ void conv_tf32(const float4* __restrict__ src, float4* __restrict__ dst, int n4)
{
    const int i = blockIdx.x * blockDim.x + threadIdx.x;
    if (i < n4) {
        float4 v = src[i];
        v.x = __uint_as_float(f2tf(v.x));
        v.y = __uint_as_float(f2tf(v.y));
        v.z = __uint_as_float(f2tf(v.z));
        v.w = __uint_as_float(f2tf(v.w));
        dst[i] = v;
    }
}

// ---------------------------------------------------------------------------
// norms (f32 in, tf32 out)
// ---------------------------------------------------------------------------
__device__ __forceinline__ float block_sum_256(float v) {
    __shared__ float red[8];
#pragma unroll
    for (int o = 16; o; o >>= 1) v += __shfl_xor_sync(0xffffffffu, v, o);
    const int w = threadIdx.x >> 5, l = threadIdx.x & 31;
    if (l == 0) red[w] = v;
    __syncthreads();
    float r = 0.f;
    if (w == 0) {
        r = (l < 8) ? red[l] : 0.f;
#pragma unroll
        for (int o = 4; o; o >>= 1) r += __shfl_xor_sync(0xffffffffu, r, o);
    }
    return r;
}

__global__ void rms_qa(const float* __restrict__ x, float* __restrict__ y,
                       const float* __restrict__ w)
{
    const float* row = x + (size_t)blockIdx.x * 1536;
    float* dst       = y + (size_t)blockIdx.x * 1536;
    float ss = 0.f;
    for (int j = threadIdx.x; j < 1536; j += 256) { const float v = row[j]; ss += v * v; }
    const float tot = block_sum_256(ss);
    __shared__ float s_sc;
    if (threadIdx.x == 0) s_sc = rsqrtf(tot / 1536.f + 1e-6f);
    __syncthreads();
    const float sc = s_sc;
    for (int j = threadIdx.x; j < 1536; j += 256)
        dst[j] = __uint_as_float(f2tf(row[j] * sc * w[j]));
}

__global__ void rms_kv_kpe(const float* __restrict__ ckv, float* __restrict__ ckvn,
                           const float* __restrict__ w, float* __restrict__ out)
{
    const int t = blockIdx.x;
    const float* row = ckv + (size_t)t * 576;
    float ss = 0.f;
    for (int j = threadIdx.x; j < R_KV; j += 256) { const float v = row[j]; ss += v * v; }
    const float tot = block_sum_256(ss);
    __shared__ float s_sc;
    if (threadIdx.x == 0) s_sc = rsqrtf(tot / (float)R_KV + 1e-6f);
    __syncthreads();
    const float sc = s_sc;
    for (int j = threadIdx.x; j < R_KV; j += 256)
        ckvn[(size_t)t * R_KV + j] = __uint_as_float(f2tf(row[j] * sc * w[j]));

    // k_pe scatter (raw f32, deepseek-transposed) to all 32 key heads
    const int b = t >> 12;
    const int s = t & (SEQ - 1);
    const int j  = threadIdx.x & 63;
    const int hg = threadIdx.x >> 6;
    const float v = row[R_KV + j];
    const int col = D_NOPE + (j >> 1) + ((j & 1) << 5);
#pragma unroll
    for (int hh = 0; hh < 8; hh++) {
        const int h = hg * 8 + hh;
        out[((size_t)((b * OUT_CH + NHEAD + h) * SEQ + s)) * D_Q + col] = v;
    }
}

__global__ void zero_vpad(float* __restrict__ out)
{
    const int idx = blockIdx.x * blockDim.x + threadIdx.x;
    const int f = idx & 15;
    const int s = (idx >> 4) & (SEQ - 1);
    const int h = (idx >> 16) & 31;
    const int b = idx >> 21;
    float4* p = (float4*)(out + ((size_t)((b * OUT_CH + 2 * NHEAD + h) * SEQ + s)) * D_Q + D_NOPE) + f;
    *p = make_float4(0.f, 0.f, 0.f, 0.f);
}

// ---------------------------------------------------------------------------
extern "C" void kernel_launch(void* const* d_in, const int* in_sizes, int n_in,
                              void* d_out, int out_size)
{
    const float* hidden    = (const float*)d_in[0];
    const float* q_a_w     = (const float*)d_in[1];
    const float* q_b_w     = (const float*)d_in[2];
    const float* kv_a_w    = (const float*)d_in[3];
    const float* kv_b_w    = (const float*)d_in[4];
    const float* q_a_ln_w  = (const float*)d_in[5];
    const float* kv_a_ln_w = (const float*)d_in[6];
    float* out = (float*)d_out;

    float *ht, *w12, *w3, *w4, *qa, *qat, *ckv, *ckvnt;
    cudaGetSymbolAddress((void**)&ht,    g_ht);
    cudaGetSymbolAddress((void**)&w12,   g_w12);
    cudaGetSymbolAddress((void**)&w3,    g_w3);
    cudaGetSymbolAddress((void**)&w4,    g_w4);
    cudaGetSymbolAddress((void**)&qa,    g_qa);
    cudaGetSymbolAddress((void**)&qat,   g_qat);
    cudaGetSymbolAddress((void**)&ckv,   g_ckv);
    cudaGetSymbolAddress((void**)&ckvnt, g_ckvnt);

    const int SMEM = 2 * 26112 * 4;   // 208896 B
    cudaFuncSetAttribute(gemm_tf32<1>, cudaFuncAttributeMaxDynamicSharedMemorySize, SMEM);
    cudaFuncSetAttribute(gemm_tf32<2>, cudaFuncAttributeMaxDynamicSharedMemorySize, SMEM);
    cudaFuncSetAttribute(gemm_tf32<3>, cudaFuncAttributeMaxDynamicSharedMemorySize, SMEM);

    // 1) pre-convert inputs to tf32 (rna); down-proj weights packed together
    auto conv = [&](const float* s, float* d, int n) {
        const int n4 = n >> 2;
        conv_tf32<<<(n4 + 255) / 256, 256>>>((const float4*)s, (float4*)d, n4);
    };
    conv(hidden, ht, 33554432);
    conv(q_a_w,  w12,           6291456);
    conv(kv_a_w, w12 + 6291456, 2359296);
    conv(q_b_w,  w3, 9437184);
    conv(kv_b_w, w4, 4194304);

    const dim3 blk(256);

    // 2) merged down-projection: [qa | ckv] = ht @ [q_a_w | kv_a_w]^T
    gemm_tf32<3><<<dim3(9, 64), blk, SMEM>>>(ht, w12, qa, ckv, 2112, 4096);

    // 3) norms + k_pe scatter + value padding
    rms_qa    <<<TOKENS, 256>>>(qa, qat, q_a_ln_w);
    rms_kv_kpe<<<TOKENS, 256>>>(ckv, ckvnt, kv_a_ln_w, out);
    zero_vpad <<<(2 * NHEAD * SEQ * 16) / 256, 256>>>(out);

    // 4) up-projections with fused scatter epilogues
    gemm_tf32<1><<<dim3(24, 64), blk, SMEM>>>(qat,   w3, out, nullptr, 6144, 1536);
    gemm_tf32<2><<<dim3(32, 64), blk, SMEM>>>(ckvnt, w4, out, nullptr, 8192, 512);
}

// round 10
// speedup vs baseline: 2.5007x; 1.0229x over previous
#include <cuda_runtime.h>
#include <cstdint>

// ---------------------------------------------------------------------------
// MLA QKV projection — R10: mma.sync TF32, 4-stage BK=32 cp.async pipeline.
//   Block 128(tok) x 256(feat), 8 warps, warp tile 64x64, ldmatrix fragments.
//   One __syncthreads per k-iter; loads issued before compute (3 in flight).
//   Hidden read raw (HW tf32 truncation); weights/activations rna-converted.
//   Merged launches: 1 down-GEMM, 1 rms+kpe+vpad, 1 dual up-GEMM.
// ---------------------------------------------------------------------------

#define TOKENS   8192
#define SEQ      4096
#define NHEAD    32
#define D_Q      192
#define D_NOPE   128
#define R_KV     512
#define OUT_CH   96

// ---------------- scratch (__device__ globals; no allocs allowed) ----------
__device__ float g_w12  [8650752];    // [q_a_w | kv_a_w] tf32 (2112*4096)
__device__ float g_w3   [9437184];    // q_b_w   tf32  (6144*1536)
__device__ float g_w4   [4194304];    // kv_b_w  tf32  (8192*512)
__device__ float g_qa   [12582912];   // f32 down-proj out (8192*1536)
__device__ float g_qat  [12582912];   // tf32 normed qa
__device__ float g_ckv  [4718592];    // f32 down-proj out (8192*576)
__device__ float g_ckvnt[4194304];    // tf32 normed ckv (8192*512)

__device__ __forceinline__ uint32_t f2tf(float f) {
    uint32_t r; asm("cvt.rna.tf32.f32 %0, %1;" : "=r"(r) : "f"(f)); return r;
}

__device__ __forceinline__ void mma8(float c[4], const uint32_t a[4], const uint32_t b[2]) {
    asm volatile(
        "mma.sync.aligned.m16n8k8.row.col.f32.tf32.tf32.f32 "
        "{%0,%1,%2,%3},{%4,%5,%6,%7},{%8,%9},{%0,%1,%2,%3};"
        : "+f"(c[0]), "+f"(c[1]), "+f"(c[2]), "+f"(c[3])
        : "r"(a[0]), "r"(a[1]), "r"(a[2]), "r"(a[3]), "r"(b[0]), "r"(b[1]));
}

#define LDSM4(r, addr) \
    asm volatile("ldmatrix.sync.aligned.m8n8.x4.shared.b16 {%0,%1,%2,%3}, [%4];" \
        : "=r"((r)[0]), "=r"((r)[1]), "=r"((r)[2]), "=r"((r)[3]) : "r"(addr))

__device__ __forceinline__ void cpa16(uint32_t dst, const void* src, int nbytes) {
    asm volatile("cp.async.cg.shared.global [%0], [%1], 16, %2;"
                 :: "r"(dst), "l"(src), "r"(nbytes));
}
#define CPA_COMMIT() asm volatile("cp.async.commit_group;" ::: "memory")
#define CPA_WAIT(n)  asm volatile("cp.async.wait_group %0;" :: "n"(n) : "memory")

// epi modes: 1 = query scatter, 2 = key/value scatter, 3 = down (qa|ckv split)
__device__ __forceinline__ void epi_store(int epi, float* __restrict__ C,
                                          float* __restrict__ C2, int t, int n, float v) {
    if (epi == 3) {
        if (n < 1536) C [(size_t)t * 1536 + n] = v;
        else          C2[(size_t)t * 576 + (n - 1536)] = v;
        return;
    }
    const int b = t >> 12;
    const int s = t & (SEQ - 1);
    if (epi == 1) {
        const int h = n / D_Q;
        const int d = n - h * D_Q;
        int col;
        if (d < D_NOPE) col = d;
        else {
            const int j = d - D_NOPE;
            col = D_NOPE + (j >> 1) + ((j & 1) << 5);
        }
        C[((size_t)((b * OUT_CH + h) * SEQ + s)) * D_Q + col] = v;
    } else {
        const int h  = n >> 8;
        const int d  = n & 255;
        const int ch = (d < 128) ? (NHEAD + h) : (2 * NHEAD + h);
        C[((size_t)((b * OUT_CH + ch) * SEQ + s)) * D_Q + (d & 127)] = v;
    }
}

// ---------------------------------------------------------------------------
// GEMM core: C = A[M,K](tokens) * W[N,K]^T(features)
// BM=128, BN=256, BK=32; 256 threads = 8 warps (2x4), warp tile 64x64.
// smem row stride 36; stage = 13824 floats (55296 B); 4 stages = 221184 B.
// Pipeline: 3 tiles in flight, one __syncthreads per iteration.
// ---------------------------------------------------------------------------
__device__ __forceinline__ void
gemm_core(const float* __restrict__ A, const float* __restrict__ W,
          float* __restrict__ C, float* __restrict__ C2,
          int N, int K, int t0, int n0, int epi, float* smem)
{
    const int tid   = threadIdx.x;
    const int lane  = tid & 31;
    const int wrp   = tid >> 5;
    const int warpM = wrp >> 2;
    const int warpN = wrp & 3;

    float acc[4][8][4];
#pragma unroll
    for (int i = 0; i < 4; i++)
#pragma unroll
        for (int j = 0; j < 8; j++)
#pragma unroll
            for (int k = 0; k < 4; k++) acc[i][j][k] = 0.f;

    const int KT = K >> 5;

    auto load_tile = [&](int s, int kt) {
        const int kk = kt * 32;
        float* sA = smem + s * 13824;
        float* sB = sA + 4608;
#pragma unroll
        for (int i = 0; i < 4; i++) {
            const int f = tid + i * 256;
            const int row = f >> 3, cq = (f & 7) << 2;
            const uint32_t dst = (uint32_t)__cvta_generic_to_shared(sA + row * 36 + cq);
            cpa16(dst, A + (size_t)(t0 + row) * K + kk + cq, 16);
        }
#pragma unroll
        for (int i = 0; i < 8; i++) {
            const int f = tid + i * 256;
            const int row = f >> 3, cq = (f & 7) << 2;
            const int gn = n0 + row;
            const uint32_t dst = (uint32_t)__cvta_generic_to_shared(sB + row * 36 + cq);
            const int ok = (gn < N) ? 16 : 0;
            cpa16(dst, W + (size_t)(ok ? gn : 0) * K + kk + cq, ok);
        }
        CPA_COMMIT();
    };

    load_tile(0, 0);
    if (KT > 1) load_tile(1, 1);
    if (KT > 2) load_tile(2, 2);

    const int lm = lane >> 3;
    const int lr = lane & 7;
    const int ar = warpM * 64 + (lm & 1) * 8 + lr;
    const int ak = (lm >> 1) * 4;
    const int br = warpN * 64 + (lm >> 1) * 8 + lr;
    const int bk = (lm & 1) * 4;

    for (int kt = 0; kt < KT; kt++) {
        const int rem = KT - 1 - kt;
        if (rem >= 2) CPA_WAIT(2);
        else if (rem == 1) CPA_WAIT(1);
        else CPA_WAIT(0);
        __syncthreads();

        if (kt + 3 < KT) load_tile((kt + 3) & 3, kt + 3);

        float* sA = smem + (kt & 3) * 13824;
        float* sB = sA + 4608;

        uint32_t aAddr[4], bAddr[4];
#pragma unroll
        for (int mi = 0; mi < 4; mi++)
            aAddr[mi] = (uint32_t)__cvta_generic_to_shared(sA + (ar + mi * 16) * 36 + ak);
#pragma unroll
        for (int p = 0; p < 4; p++)
            bAddr[p] = (uint32_t)__cvta_generic_to_shared(sB + (br + p * 16) * 36 + bk);

#pragma unroll
        for (int ks = 0; ks < 4; ks++) {
            uint32_t a[4][4], b[4][4];
#pragma unroll
            for (int mi = 0; mi < 4; mi++) LDSM4(a[mi], aAddr[mi] + ks * 32);
#pragma unroll
            for (int p = 0; p < 4; p++)   LDSM4(b[p],  bAddr[p]  + ks * 32);
#pragma unroll
            for (int mi = 0; mi < 4; mi++)
#pragma unroll
                for (int p = 0; p < 4; p++) {
                    mma8(acc[mi][2 * p],     a[mi], &b[p][0]);
                    mma8(acc[mi][2 * p + 1], a[mi], &b[p][2]);
                }
        }
    }

    // epilogue
#pragma unroll
    for (int mi = 0; mi < 4; mi++) {
        const int row = t0 + warpM * 64 + mi * 16 + (lane >> 2);
#pragma unroll
        for (int ni = 0; ni < 8; ni++) {
            const int col = n0 + warpN * 64 + ni * 8 + ((lane & 3) << 1);
            if (col < N) {   // N even -> col+1 also valid
                epi_store(epi, C, C2, row,     col,     acc[mi][ni][0]);
                epi_store(epi, C, C2, row,     col + 1, acc[mi][ni][1]);
                epi_store(epi, C, C2, row + 8, col,     acc[mi][ni][2]);
                epi_store(epi, C, C2, row + 8, col + 1, acc[mi][ni][3]);
            }
        }
    }
}

// down-projection: [qa | ckv] = hidden(raw f32, HW-truncated) @ w12^T
__global__ void __launch_bounds__(256, 1)
gemm_down(const float* __restrict__ A, const float* __restrict__ W,
          float* __restrict__ C, float* __restrict__ C2)
{
    extern __shared__ float smem[];
    gemm_core(A, W, C, C2, 2112, 4096, blockIdx.y * 128, blockIdx.x * 256, 3, smem);
}

// merged up-projections: blocks [0,24) = query (K=1536), [24,56) = kv (K=512)
__global__ void __launch_bounds__(256, 1)
gemm_up(const float* __restrict__ Aq, const float* __restrict__ Wq,
        const float* __restrict__ Akv, const float* __restrict__ Wkv,
        float* __restrict__ out)
{
    extern __shared__ float smem[];
    const int bx = blockIdx.x;
    const int t0 = blockIdx.y * 128;
    if (bx < 24)
        gemm_core(Aq,  Wq,  out, nullptr, 6144, 1536, t0, bx * 256, 1, smem);
    else
        gemm_core(Akv, Wkv, out, nullptr, 8192, 512,  t0, (bx - 24) * 256, 2, smem);
}

// ---------------------------------------------------------------------------
// f32 -> tf32(rna) pre-conversion (weights only)
// ---------------------------------------------------------------------------
__global__ void conv_tf32(const float4* __restrict__ src, float4* __restrict__ dst, int n4)
{
    const int i = blockIdx.x * blockDim.x + threadIdx.x;
    if (i < n4) {
        float4 v = src[i];
        v.x = __uint_as_float(f2tf(v.x));
        v.y = __uint_as_float(f2tf(v.y));
        v.z = __uint_as_float(f2tf(v.z));
        v.w = __uint_as_float(f2tf(v.w));
        dst[i] = v;
    }
}

// ---------------------------------------------------------------------------
// merged norms: blocks [0,8192) rms(qa); [8192,16384) rms(ckv)+kpe+vpad
// ---------------------------------------------------------------------------
__device__ __forceinline__ float block_sum_256(float v) {
    __shared__ float red[8];
#pragma unroll
    for (int o = 16; o; o >>= 1) v += __shfl_xor_sync(0xffffffffu, v, o);
    const int w = threadIdx.x >> 5, l = threadIdx.x & 31;
    if (l == 0) red[w] = v;
    __syncthreads();
    float r = 0.f;
    if (w == 0) {
        r = (l < 8) ? red[l] : 0.f;
#pragma unroll
        for (int o = 4; o; o >>= 1) r += __shfl_xor_sync(0xffffffffu, r, o);
    }
    return r;
}

__global__ void rms_all(const float* __restrict__ qa, float* __restrict__ qat,
                        const float* __restrict__ qw,
                        const float* __restrict__ ckv, float* __restrict__ ckvnt,
                        const float* __restrict__ kw, float* __restrict__ out)
{
    __shared__ float s_sc;
    const int bid = blockIdx.x;
    if (bid < TOKENS) {
        const float* row = qa + (size_t)bid * 1536;
        float* dst       = qat + (size_t)bid * 1536;
        float ss = 0.f;
        for (int j = threadIdx.x; j < 1536; j += 256) { const float v = row[j]; ss += v * v; }
        const float tot = block_sum_256(ss);
        if (threadIdx.x == 0) s_sc = rsqrtf(tot / 1536.f + 1e-6f);
        __syncthreads();
        const float sc = s_sc;
        for (int j = threadIdx.x; j < 1536; j += 256)
            dst[j] = __uint_as_float(f2tf(row[j] * sc * qw[j]));
    } else {
        const int t = bid - TOKENS;
        const float* row = ckv + (size_t)t * 576;
        float ss = 0.f;
        for (int j = threadIdx.x; j < R_KV; j += 256) { const float v = row[j]; ss += v * v; }
        const float tot = block_sum_256(ss);
        if (threadIdx.x == 0) s_sc = rsqrtf(tot / (float)R_KV + 1e-6f);
        __syncthreads();
        const float sc = s_sc;
        for (int j = threadIdx.x; j < R_KV; j += 256)
            ckvnt[(size_t)t * R_KV + j] = __uint_as_float(f2tf(row[j] * sc * kw[j]));

        const int b = t >> 12;
        const int s = t & (SEQ - 1);
        // k_pe scatter (raw f32, deepseek-transposed) to all 32 key heads
        {
            const int j  = threadIdx.x & 63;
            const int hg = threadIdx.x >> 6;
            const float v = row[R_KV + j];
            const int col = D_NOPE + (j >> 1) + ((j & 1) << 5);
#pragma unroll
            for (int hh = 0; hh < 8; hh++) {
                const int h = hg * 8 + hh;
                out[((size_t)((b * OUT_CH + NHEAD + h) * SEQ + s)) * D_Q + col] = v;
            }
        }
        // value padding zero: out[b, 64+h, s, 128:192]
#pragma unroll
        for (int i = 0; i < 2; i++) {
            const int idx = threadIdx.x + i * 256;   // 0..511
            const int h = idx >> 4, f = idx & 15;
            float4* p = (float4*)(out + ((size_t)((b * OUT_CH + 2 * NHEAD + h) * SEQ + s)) * D_Q + D_NOPE) + f;
            *p = make_float4(0.f, 0.f, 0.f, 0.f);
        }
    }
}

// ---------------------------------------------------------------------------
extern "C" void kernel_launch(void* const* d_in, const int* in_sizes, int n_in,
                              void* d_out, int out_size)
{
    const float* hidden    = (const float*)d_in[0];
    const float* q_a_w     = (const float*)d_in[1];
    const float* q_b_w     = (const float*)d_in[2];
    const float* kv_a_w    = (const float*)d_in[3];
    const float* kv_b_w    = (const float*)d_in[4];
    const float* q_a_ln_w  = (const float*)d_in[5];
    const float* kv_a_ln_w = (const float*)d_in[6];
    float* out = (float*)d_out;

    float *w12, *w3, *w4, *qa, *qat, *ckv, *ckvnt;
    cudaGetSymbolAddress((void**)&w12,   g_w12);
    cudaGetSymbolAddress((void**)&w3,    g_w3);
    cudaGetSymbolAddress((void**)&w4,    g_w4);
    cudaGetSymbolAddress((void**)&qa,    g_qa);
    cudaGetSymbolAddress((void**)&qat,   g_qat);
    cudaGetSymbolAddress((void**)&ckv,   g_ckv);
    cudaGetSymbolAddress((void**)&ckvnt, g_ckvnt);

    const int SMEM = 4 * 13824 * 4;   // 221184 B
    cudaFuncSetAttribute(gemm_down, cudaFuncAttributeMaxDynamicSharedMemorySize, SMEM);
    cudaFuncSetAttribute(gemm_up,   cudaFuncAttributeMaxDynamicSharedMemorySize, SMEM);

    // 1) rna-convert weights (hidden stays raw: HW truncates to tf32)
    auto conv = [&](const float* s, float* d, int n) {
        const int n4 = n >> 2;
        conv_tf32<<<(n4 + 255) / 256, 256>>>((const float4*)s, (float4*)d, n4);
    };
    conv(q_a_w,  w12,           6291456);
    conv(kv_a_w, w12 + 6291456, 2359296);
    conv(q_b_w,  w3, 9437184);
    conv(kv_b_w, w4, 4194304);

    const dim3 blk(256);

    // 2) merged down-projection: [qa | ckv] = hidden @ [q_a_w | kv_a_w]^T
    gemm_down<<<dim3(9, 64), blk, SMEM>>>(hidden, w12, qa, ckv);

    // 3) merged norms + k_pe scatter + value padding
    rms_all<<<2 * TOKENS, 256>>>(qa, qat, q_a_ln_w, ckv, ckvnt, kv_a_ln_w, out);

    // 4) merged up-projections with fused scatter epilogues
    gemm_up<<<dim3(56, 64), blk, SMEM>>>(qat, w3, ckvnt, w4, out);
}